// round 7
// baseline (speedup 1.0000x reference)
#include <cuda_runtime.h>
#include <float.h>

#define PH 7
#define PW 7
#define BD 2
#define ND 96
#define HD 64
#define WD 64
#define CD 128

#define NBINS (BD * ND * PH * PW)   // 9408
#define UN 8                        // prefetch depth (MLP)
#define RSPLIT 4                    // warps per bin (row interleave)

__device__ __forceinline__ void fmax4(float4& a, const float4& v) {
    a.x = fmaxf(a.x, v.x);
    a.y = fmaxf(a.y, v.y);
    a.z = fmaxf(a.z, v.z);
    a.w = fmaxf(a.w, v.w);
}

__global__ void __launch_bounds__(32 * RSPLIT)
roipool_kernel(const float* __restrict__ fmap,
               const float* __restrict__ rois,
               float* __restrict__ out) {
    const int warp = threadIdx.x >> 5;
    const int lane = threadIdx.x & 31;
    const int bin  = blockIdx.x;              // ((b*N+n)*PH+ph)*PW+pw

    const int pw  = bin % PW;
    const int ph  = (bin / PW) % PH;
    const int roi = bin / (PH * PW);          // b*N+n
    const int b   = roi / ND;

    // roi = [x_center, y_center, width, height]
    const float4 r4 = __ldg((const float4*)(rois) + roi);
    const float xc = r4.x, yc = r4.y, ww = r4.z, hh = r4.w;

    // rows (y axis: yc, hh)
    const float halfh = floorf(hh * 0.5f);
    const int ys   = (int)(yc - halfh);
    const int ye   = (int)(yc + halfh);
    const int lenh = ye - ys;
    const int sth  = max(lenh / PH, 1);
    const int ry0  = ph * sth;
    const int ry1  = (ph == PH - 1) ? lenh : ry0 + sth;
    const int y0   = max(ys + ry0, 0);
    const int y1   = min(ys + ry1, HD);

    // cols (x axis: xc, ww)
    const float halfw = floorf(ww * 0.5f);
    const int xs   = (int)(xc - halfw);
    const int xe   = (int)(xc + halfw);
    const int lenw = xe - xs;
    const int stw  = max(lenw / PW, 1);
    const int rx0  = pw * stw;
    const int rx1  = (pw == PW - 1) ? lenw : rx0 + stw;
    const int x0   = max(xs + rx0, 0);
    const int x1   = min(xs + rx1, WD);

    const int nx = x1 - x0;
    // this warp's rows: y0+warp, y0+warp+RSPLIT, ...
    const int myrows = (y1 - y0 - warp + RSPLIT - 1) / RSPLIT;  // may be <=0
    const int npix   = (myrows > 0) ? myrows * nx : 0;

    float4 acc = make_float4(-FLT_MAX, -FLT_MAX, -FLT_MAX, -FLT_MAX);

    // lane = 4-channel group; incremental walk over this warp's rows,
    // software-pipelined (UN loads in flight, data served by L2/L1).
    const float4* p = (const float4*)(fmap + ((size_t)b * HD) * WD * CD)
                      + ((y0 + warp) * WD + x0) * (CD / 4) + lane;
    const int rowskip = (RSPLIT * WD - nx) * (CD / 4);
    int xi = 0;

#define ADV { p += (CD / 4); if (++xi == nx) { xi = 0; p += rowskip; } }

    float4 buf[UN];
    int i = 0;
    for (; i + UN <= npix; i += UN) {
        #pragma unroll
        for (int k = 0; k < UN; k++) { buf[k] = __ldg(p); ADV }
        #pragma unroll
        for (int k = 0; k < UN; k++) fmax4(acc, buf[k]);
    }
    for (; i < npix; i++) {
        float4 v = __ldg(p); ADV
        fmax4(acc, v);
    }

    __shared__ float4 smax[RSPLIT][32];
    smax[warp][lane] = acc;
    __syncthreads();

    if (warp == 0) {
        float4 a = smax[0][lane];
        #pragma unroll
        for (int w = 1; w < RSPLIT; w++) fmax4(a, smax[w][lane]);
        ((float4*)out)[(size_t)bin * 32 + lane] = a;
    }
}

extern "C" void kernel_launch(void* const* d_in, const int* in_sizes, int n_in,
                              void* d_out, int out_size) {
    const float* fmap = (const float*)d_in[0];
    const float* rois = (const float*)d_in[1];
    float* out = (float*)d_out;
    roipool_kernel<<<NBINS, 32 * RSPLIT>>>(fmap, rois, out);
}